// round 8
// baseline (speedup 1.0000x reference)
#include <cuda_runtime.h>
#include <cuda_bf16.h>

#define BATCH 128
#define TSTEPS 1024
#define IDIM 256
#define HDIM 512
#define GDIM 2048

typedef unsigned long long ull;

// ------------------------------- scratch ----------------------------------
__device__ float g_xw[(size_t)TSTEPS * BATCH * GDIM];   // [t][b][g'] (1 GiB)
__device__ float g_Wsm[128 * 16 * 512];                 // [cta][gate*4+kl][j]
__device__ float g_Wih_t[IDIM * GDIM];                  // [i][g']
__device__ float g_bias[GDIM];                          // reordered b_ih+b_hh
__device__ float g_h[2 * BATCH * HDIM];                 // double-buffered h
__device__ unsigned g_bar;

// ----------------------------- f32x2 helpers ------------------------------
__device__ __forceinline__ ull pk2(float lo, float hi) {
    ull r; asm("mov.b64 %0, {%1, %2};" : "=l"(r) : "f"(lo), "f"(hi)); return r;
}
__device__ __forceinline__ void fma2(ull& d, ull a, ull b) {
    asm("fma.rn.f32x2 %0, %1, %2, %0;" : "+l"(d) : "l"(a), "l"(b));
}
__device__ __forceinline__ float2 upk2(ull v) {
    float2 r; asm("mov.b64 {%0, %1}, %2;" : "=f"(r.x), "=f"(r.y) : "l"(v)); return r;
}
__device__ __forceinline__ void ldcg_v2u64(ull& a, ull& b, const float* p) {
    asm volatile("ld.global.cg.v2.u64 {%0,%1}, [%2];" : "=l"(a), "=l"(b) : "l"(p));
}

// ------------------------------ init kernel -------------------------------
// Column reorder: g' = 16*cta + 4*kl + gate, khid = 4*cta + kl.
// Decode: gate=g'&3, kl=(g'>>2)&3, khid=((g'>>4)<<2)+kl.
__global__ void init_kernel(const float* __restrict__ W_ih,
                            const float* __restrict__ W_hh,
                            const float* __restrict__ b_ih,
                            const float* __restrict__ b_hh) {
    int idx = blockIdx.x * blockDim.x + threadIdx.x;
    int stride = gridDim.x * blockDim.x;

    // g_Wsm[cta][gate*4+kl][j] = W_hh[gate*512 + cta*4 + kl][j]
    for (int p = idx; p < 128 * 16 * 512; p += stride) {
        int cta  = p >> 13;
        int row  = (p >> 9) & 15;     // gate*4 + kl
        int j    = p & 511;
        int gate = row >> 2, kl = row & 3;
        int khid = cta * 4 + kl;
        g_Wsm[p] = W_hh[(size_t)(gate * 512 + khid) * 512 + j];
    }
    // g_Wih_t[i][g'] = W_ih[gate*512 + khid][i]
    for (int p = idx; p < IDIM * GDIM; p += stride) {
        int i = p >> 11, g = p & 2047;
        int gate = g & 3, kl = (g >> 2) & 3, khid = ((g >> 4) << 2) + kl;
        g_Wih_t[p] = W_ih[(size_t)(gate * 512 + khid) * 256 + i];
    }
    for (int p = idx; p < GDIM; p += stride) {
        int gate = p & 3, kl = (p >> 2) & 3, khid = ((p >> 4) << 2) + kl;
        g_bias[p] = b_ih[gate * 512 + khid] + b_hh[gate * 512 + khid];
    }
    if (idx == 0) g_bar = 0u;
}

// ------------------------------- xW GEMM ----------------------------------
// C[m=(t,bhalf)][n=g'] = x[b][t][:] . g_Wih_t[:][n] + bias[n]
#define GM_BK 32
#define AS_STRIDE 68

__global__ __launch_bounds__(256) void xw_gemm(const float* __restrict__ x) {
    __shared__ float As[GM_BK * AS_STRIDE];   // [k][row], 64 rows
    __shared__ float Bs[GM_BK * 128];         // [k][n]

    const int by = blockIdx.y;                // 0..2047
    const int t  = by >> 1;
    const int b0 = (by & 1) * 64;
    const int n0 = blockIdx.x * 128;
    const int tid = threadIdx.x;
    const int tm = tid & 15;
    const int tn8 = (tid >> 4) * 8;

    const float* xbase = x + ((size_t)b0 * TSTEPS + t) * IDIM;

    ull acc[4][4];
    #pragma unroll
    for (int m = 0; m < 4; m++)
        #pragma unroll
        for (int p = 0; p < 4; p++) acc[m][p] = 0ull;

    for (int k0 = 0; k0 < IDIM; k0 += GM_BK) {
        #pragma unroll
        for (int l = 0; l < 2; l++) {
            int idx4 = tid + l * 256;                  // 0..511
            int k4 = (idx4 & 7) * 4;
            int row = idx4 >> 3;
            float4 v = *(const float4*)(xbase + (size_t)row * (TSTEPS * IDIM) + k0 + k4);
            As[(k4 + 0) * AS_STRIDE + row] = v.x;
            As[(k4 + 1) * AS_STRIDE + row] = v.y;
            As[(k4 + 2) * AS_STRIDE + row] = v.z;
            As[(k4 + 3) * AS_STRIDE + row] = v.w;
        }
        #pragma unroll
        for (int l = 0; l < 4; l++) {
            int idx4 = tid + l * 256;                  // 0..1023
            int n4 = (idx4 & 31) * 4;
            int k  = idx4 >> 5;
            *(float4*)(&Bs[k * 128 + n4]) =
                *(const float4*)(g_Wih_t + (size_t)(k0 + k) * GDIM + n0 + n4);
        }
        __syncthreads();

        #pragma unroll
        for (int k = 0; k < GM_BK; k++) {
            float4 a  = *(const float4*)(&As[k * AS_STRIDE + tm * 4]);
            float4 bA = *(const float4*)(&Bs[k * 128 + tn8]);
            float4 bB = *(const float4*)(&Bs[k * 128 + tn8 + 4]);
            ull b01 = pk2(bA.x, bA.y), b23 = pk2(bA.z, bA.w);
            ull b45 = pk2(bB.x, bB.y), b67 = pk2(bB.z, bB.w);
            ull a2;
            a2 = pk2(a.x, a.x);
            fma2(acc[0][0], a2, b01); fma2(acc[0][1], a2, b23);
            fma2(acc[0][2], a2, b45); fma2(acc[0][3], a2, b67);
            a2 = pk2(a.y, a.y);
            fma2(acc[1][0], a2, b01); fma2(acc[1][1], a2, b23);
            fma2(acc[1][2], a2, b45); fma2(acc[1][3], a2, b67);
            a2 = pk2(a.z, a.z);
            fma2(acc[2][0], a2, b01); fma2(acc[2][1], a2, b23);
            fma2(acc[2][2], a2, b45); fma2(acc[2][3], a2, b67);
            a2 = pk2(a.w, a.w);
            fma2(acc[3][0], a2, b01); fma2(acc[3][1], a2, b23);
            fma2(acc[3][2], a2, b45); fma2(acc[3][3], a2, b67);
        }
        __syncthreads();
    }

    float4 bz0 = *(const float4*)(g_bias + n0 + tn8);
    float4 bz1 = *(const float4*)(g_bias + n0 + tn8 + 4);
    #pragma unroll
    for (int m = 0; m < 4; m++) {
        int brow = b0 + tm * 4 + m;
        float* op = g_xw + ((size_t)t * BATCH + brow) * GDIM + n0 + tn8;
        float2 c0 = upk2(acc[m][0]), c1 = upk2(acc[m][1]);
        float2 c2 = upk2(acc[m][2]), c3 = upk2(acc[m][3]);
        *(float4*)op       = make_float4(c0.x + bz0.x, c0.y + bz0.y, c1.x + bz0.z, c1.y + bz0.w);
        *(float4*)(op + 4) = make_float4(c2.x + bz1.x, c2.y + bz1.y, c3.x + bz1.z, c3.y + bz1.w);
    }
}

// ---------------------------- recurrent kernel ----------------------------
#define JP 516   // padded j-stride (conflict-free LDS.128 across kl)

__global__ __launch_bounds__(512, 1) void lstm_rec() {
    __shared__ float sW[16 * JP];

    const int cta = blockIdx.x;    // 0..127
    const int tid = threadIdx.x;   // 0..511

    {   // stage this CTA's W_hh slice once (constant over all steps)
        const float* wsrc = g_Wsm + (size_t)cta * 8192;
        for (int p = tid; p < 8192; p += 512) {
            int r = p >> 9, j = p & 511;
            sW[r * JP + j] = wsrc[p];
        }
    }
    __syncthreads();

    const int kl = tid & 3;
    const int b  = tid >> 2;
    const int hoff = b * HDIM;
    const int oI = (0 + kl) * JP, oF = (4 + kl) * JP;
    const int oG = (8 + kl) * JP, oO = (12 + kl) * JP;
    const float* xwp = g_xw + (size_t)b * GDIM + cta * 16 + kl * 4;
    float* hout_base = g_h + hoff + cta * 4 + kl;

    float creg = 0.0f;
    unsigned bar_t = 0;

    for (int t = 0; t < TSTEPS; t++) {
        float4 xv = *(const float4*)(xwp + (size_t)t * (BATCH * GDIM));
        ull aI = 0ull, aF = 0ull, aG = 0ull, aO = 0ull;

        if (t > 0) {
            const float* hrow = g_h + (size_t)(t & 1) * (BATCH * HDIM) + hoff;
            #pragma unroll 1
            for (int j = 0; j < HDIM; j += 16) {
                #pragma unroll
                for (int q = 0; q < 4; q++) {
                    const int jj = j + q * 4;
                    ull h0, h1;
                    ldcg_v2u64(h0, h1, hrow + jj);
                    ulonglong2 wi = *(const ulonglong2*)(&sW[oI + jj]);
                    ulonglong2 wf = *(const ulonglong2*)(&sW[oF + jj]);
                    ulonglong2 wg = *(const ulonglong2*)(&sW[oG + jj]);
                    ulonglong2 wo = *(const ulonglong2*)(&sW[oO + jj]);
                    fma2(aI, h0, wi.x); fma2(aF, h0, wf.x);
                    fma2(aG, h0, wg.x); fma2(aO, h0, wo.x);
                    fma2(aI, h1, wi.y); fma2(aF, h1, wf.y);
                    fma2(aG, h1, wg.y); fma2(aO, h1, wo.y);
                }
            }
        }

        float2 rI = upk2(aI), rF = upk2(aF), rG = upk2(aG), rO = upk2(aO);
        float pi = xv.x + rI.x + rI.y;
        float pf = xv.y + rF.x + rF.y;
        float pg = xv.z + rG.x + rG.y;
        float po = xv.w + rO.x + rO.y;

        float ig = __fdividef(1.0f, 1.0f + __expf(-pi));
        float fg = __fdividef(1.0f, 1.0f + __expf(-pf));
        float gg = 1.0f - __fdividef(2.0f, __expf(2.0f * pg) + 1.0f);
        float og = __fdividef(1.0f, 1.0f + __expf(-po));

        creg = fg * creg + ig * gg;
        float th = 1.0f - __fdividef(2.0f, __expf(2.0f * creg) + 1.0f);
        float hv = og * th;

        float* hp = hout_base + (size_t)((t + 1) & 1) * (BATCH * HDIM);
        asm volatile("st.global.cg.f32 [%0], %1;" :: "l"(hp), "f"(hv) : "memory");

        // ---- grid barrier (128 CTAs, all resident) ----
        bar_t += 128u;
        __syncthreads();
        if (tid == 0) {
            asm volatile("red.release.gpu.global.add.u32 [%0], 1;"
                         :: "l"(&g_bar) : "memory");
            unsigned v;
            do {
                asm volatile("ld.acquire.gpu.global.u32 %0, [%1];"
                             : "=r"(v) : "l"(&g_bar) : "memory");
            } while (v < bar_t);
        }
        __syncthreads();
    }
}

// ------------------------------- fc kernel --------------------------------
__global__ void fc_kernel(const float* __restrict__ fc_w,
                          const float* __restrict__ fc_b,
                          float* __restrict__ out) {
    int b = threadIdx.x;  // 128 threads
    const float* h = g_h + (size_t)b * HDIM;   // final h lives in buffer 0
    float s = 0.0f;
    #pragma unroll 8
    for (int j = 0; j < HDIM; j += 4) {
        float4 hv = *(const float4*)(h + j);
        float4 wv = *(const float4*)(fc_w + j);
        s += hv.x * wv.x + hv.y * wv.y + hv.z * wv.z + hv.w * wv.w;
    }
    out[b] = s + fc_b[0];
}

// ------------------------------- launcher ---------------------------------
extern "C" void kernel_launch(void* const* d_in, const int* in_sizes, int n_in,
                              void* d_out, int out_size) {
    const float* x    = (const float*)d_in[0];
    const float* W_ih = (const float*)d_in[1];
    const float* W_hh = (const float*)d_in[2];
    const float* b_ih = (const float*)d_in[3];
    const float* b_hh = (const float*)d_in[4];
    const float* fc_w = (const float*)d_in[5];
    const float* fc_b = (const float*)d_in[6];
    float* out = (float*)d_out;

    init_kernel<<<2048, 256>>>(W_ih, W_hh, b_ih, b_hh);
    dim3 gg(16, 2048);
    xw_gemm<<<gg, 256>>>(x);
    lstm_rec<<<128, 512>>>();
    fc_kernel<<<1, 128>>>(fc_w, fc_b, out);
}